// round 4
// baseline (speedup 1.0000x reference)
#include <cuda_runtime.h>

// All-pairs N-body gravity. Evidence says we're MUFU.RSQ-throughput bound
// (1 RSQ/pair is per-pair-constant; R2->R3 changed everything else, time flat).
// Fix: compute 1 of every 4 packed words' rsqrt via bit-magic seed + 2 packed
// Newton iterations on the (underutilized) fma/alu pipes, balancing MUFU vs fma.

#define BLOCK  256
#define JCHUNK 256
#define JP     (JCHUNK / 2)
#define EPS2   0.0001f   // SOFTENING^2

typedef unsigned long long u64;

__device__ __forceinline__ u64 pack2(float lo, float hi) {
    u64 r;
    asm("mov.b64 %0, {%1, %2};" : "=l"(r)
        : "r"(__float_as_uint(lo)), "r"(__float_as_uint(hi)));
    return r;
}
__device__ __forceinline__ void unpack2(u64 v, float& lo, float& hi) {
    unsigned a, b;
    asm("mov.b64 {%0, %1}, %2;" : "=r"(a), "=r"(b) : "l"(v));
    lo = __uint_as_float(a);
    hi = __uint_as_float(b);
}
__device__ __forceinline__ u64 f2add(u64 a, u64 b) {
    u64 r; asm("add.rn.f32x2 %0, %1, %2;" : "=l"(r) : "l"(a), "l"(b)); return r;
}
__device__ __forceinline__ u64 f2mul(u64 a, u64 b) {
    u64 r; asm("mul.rn.f32x2 %0, %1, %2;" : "=l"(r) : "l"(a), "l"(b)); return r;
}
__device__ __forceinline__ u64 f2fma(u64 a, u64 b, u64 c) {
    u64 r; asm("fma.rn.f32x2 %0, %1, %2, %3;"
               : "=l"(r) : "l"(a), "l"(b), "l"(c)); return r;
}
__device__ __forceinline__ float rsq_mufu(float x) {
    float r; asm("rsqrt.approx.f32 %0, %1;" : "=f"(r) : "f"(x)); return r;
}

__global__ void zero_out_kernel(float* __restrict__ out, int n) {
    int i = blockIdx.x * blockDim.x + threadIdx.x;
    if (i < n) out[i] = 0.0f;
}

// One packed word (2 j-bodies). NEWTON=true computes rsqrt on fma/alu pipes.
template<bool NEWTON>
__device__ __forceinline__ void body(
    const u64* sx, const u64* sy, const u64* sz, const u64* sm, int t,
    u64 nxi2, u64 nyi2, u64 nzi2, u64 eps22, u64 cnh, u64 c15,
    u64& ax2, u64& ay2, u64& az2)
{
    u64 px = sx[t], py = sy[t], pz = sz[t], pm = sm[t];

    u64 dx = f2add(px, nxi2);
    u64 dy = f2add(py, nyi2);
    u64 dz = f2add(pz, nzi2);

    u64 r2 = f2fma(dx, dx, f2fma(dy, dy, f2fma(dz, dz, eps22)));

    u64 inv;
    if (NEWTON) {
        // Bit-magic seed (alu pipe) + 2 packed Newton steps (fma pipe).
        float a, b;
        unpack2(r2, a, b);
        float s0 = __uint_as_float(0x5f375a86u - (__float_as_uint(a) >> 1));
        float s1 = __uint_as_float(0x5f375a86u - (__float_as_uint(b) >> 1));
        u64 y  = pack2(s0, s1);
        u64 nh = f2mul(r2, cnh);              // -0.5 * r2
        u64 tt = f2mul(y, y);
        y = f2mul(y, f2fma(nh, tt, c15));     // y *= 1.5 - 0.5*r2*y*y
        tt = f2mul(y, y);
        y = f2mul(y, f2fma(nh, tt, c15));
        inv = y;                              // rel err ~5e-6
    } else {
        float a, b;
        unpack2(r2, a, b);
        inv = pack2(rsq_mufu(a), rsq_mufu(b)); // 2x raw MUFU.RSQ
    }

    u64 s = f2mul(pm, f2mul(f2mul(inv, inv), inv));   // m * r2^-1.5

    ax2 = f2fma(s, dx, ax2);
    ay2 = f2fma(s, dy, ay2);
    az2 = f2fma(s, dz, az2);
}

__global__ __launch_bounds__(BLOCK)
void nbody_forces_kernel(const float* __restrict__ pos,
                         const float* __restrict__ mass,
                         float* __restrict__ out) {
    // Pair-packed SoA: word t holds bodies {jbase+2t, jbase+2t+1}.
    __shared__ u64 sx[JP], sy[JP], sz[JP], sm[JP];

    const int i     = blockIdx.x * BLOCK + threadIdx.x;
    const int jbase = blockIdx.y * JCHUNK;

    for (int t = threadIdx.x; t < JCHUNK; t += BLOCK) {
        int j = jbase + t;
        ((float*)sx)[t] = pos[3 * j + 0];
        ((float*)sy)[t] = pos[3 * j + 1];
        ((float*)sz)[t] = pos[3 * j + 2];
        ((float*)sm)[t] = mass[j];
    }
    __syncthreads();

    const float xi = pos[3 * i + 0];
    const float yi = pos[3 * i + 1];
    const float zi = pos[3 * i + 2];

    const u64 nxi2  = pack2(-xi, -xi);
    const u64 nyi2  = pack2(-yi, -yi);
    const u64 nzi2  = pack2(-zi, -zi);
    const u64 eps22 = pack2(EPS2, EPS2);
    const u64 cnh   = pack2(-0.5f, -0.5f);
    const u64 c15   = pack2(1.5f, 1.5f);

    u64 ax2 = 0ull, ay2 = 0ull, az2 = 0ull;

    // 3 MUFU-path words + 1 Newton-path word per group: balances the MUFU
    // pipe (rt~16/RSQ) against the fma pipe.
#pragma unroll 2
    for (int t = 0; t < JP; t += 4) {
        body<false>(sx, sy, sz, sm, t + 0, nxi2, nyi2, nzi2, eps22, cnh, c15,
                    ax2, ay2, az2);
        body<false>(sx, sy, sz, sm, t + 1, nxi2, nyi2, nzi2, eps22, cnh, c15,
                    ax2, ay2, az2);
        body<false>(sx, sy, sz, sm, t + 2, nxi2, nyi2, nzi2, eps22, cnh, c15,
                    ax2, ay2, az2);
        body<true >(sx, sy, sz, sm, t + 3, nxi2, nyi2, nzi2, eps22, cnh, c15,
                    ax2, ay2, az2);
    }

    float l, h;
    unpack2(ax2, l, h); atomicAdd(&out[3 * i + 0], l + h);
    unpack2(ay2, l, h); atomicAdd(&out[3 * i + 1], l + h);
    unpack2(az2, l, h); atomicAdd(&out[3 * i + 2], l + h);
}

extern "C" void kernel_launch(void* const* d_in, const int* in_sizes, int n_in,
                              void* d_out, int out_size) {
    const float* pos  = (const float*)d_in[0];   // [N,3] float32
    const float* mass = (const float*)d_in[1];   // [N]   float32
    float* out = (float*)d_out;                  // [N,3] float32

    const int n = in_sizes[0] / 3;               // 8192

    zero_out_kernel<<<(out_size + 255) / 256, 256>>>(out, out_size);

    dim3 grid(n / BLOCK, n / JCHUNK);            // 32 x 32 = 1024 CTAs
    nbody_forces_kernel<<<grid, BLOCK>>>(pos, mass, out);
}

// round 5
// speedup vs baseline: 1.0512x; 1.0512x over previous
#include <cuda_runtime.h>

// All-pairs N-body gravity, packed f32x2, diff-form (exact), IPT=2 at full
// occupancy. R3 showed 2 independent chains/thread wins; its launch_bounds
// cap threw away occupancy. This round: BLOCK=256 uncapped + IPT=2 + 1024
// CTAs -> both ILP and warp-level latency hiding. Newton path removed (R4
// falsified the MUFU-bound theory).

#define BLOCK  256
#define IPT    2
#define JCHUNK 128
#define JP     (JCHUNK / 2)
#define EPS2   0.0001f   // SOFTENING^2

typedef unsigned long long u64;

__device__ __forceinline__ u64 pack2(float lo, float hi) {
    u64 r;
    asm("mov.b64 %0, {%1, %2};" : "=l"(r)
        : "r"(__float_as_uint(lo)), "r"(__float_as_uint(hi)));
    return r;
}
__device__ __forceinline__ void unpack2(u64 v, float& lo, float& hi) {
    unsigned a, b;
    asm("mov.b64 {%0, %1}, %2;" : "=r"(a), "=r"(b) : "l"(v));
    lo = __uint_as_float(a);
    hi = __uint_as_float(b);
}
__device__ __forceinline__ u64 f2add(u64 a, u64 b) {
    u64 r; asm("add.rn.f32x2 %0, %1, %2;" : "=l"(r) : "l"(a), "l"(b)); return r;
}
__device__ __forceinline__ u64 f2mul(u64 a, u64 b) {
    u64 r; asm("mul.rn.f32x2 %0, %1, %2;" : "=l"(r) : "l"(a), "l"(b)); return r;
}
__device__ __forceinline__ u64 f2fma(u64 a, u64 b, u64 c) {
    u64 r; asm("fma.rn.f32x2 %0, %1, %2, %3;"
               : "=l"(r) : "l"(a), "l"(b), "l"(c)); return r;
}
__device__ __forceinline__ float rsq_mufu(float x) {
    float r; asm("rsqrt.approx.f32 %0, %1;" : "=f"(r) : "f"(x)); return r;
}

__global__ void zero_out_kernel(float* __restrict__ out, int n) {
    int i = blockIdx.x * blockDim.x + threadIdx.x;
    if (i < n) out[i] = 0.0f;
}

__global__ __launch_bounds__(BLOCK)
void nbody_forces_kernel(const float* __restrict__ pos,
                         const float* __restrict__ mass,
                         float* __restrict__ out) {
    // Pair-packed SoA: word t holds bodies {jbase+2t, jbase+2t+1}.
    __shared__ u64 sx[JP], sy[JP], sz[JP], sm[JP];

    const int i0    = blockIdx.x * (BLOCK * IPT) + threadIdx.x;
    const int i1    = i0 + BLOCK;
    const int jbase = blockIdx.y * JCHUNK;

    if (threadIdx.x < JCHUNK) {
        int t = threadIdx.x;
        int j = jbase + t;
        ((float*)sx)[t] = pos[3 * j + 0];
        ((float*)sy)[t] = pos[3 * j + 1];
        ((float*)sz)[t] = pos[3 * j + 2];
        ((float*)sm)[t] = mass[j];
    }
    __syncthreads();

    const u64 nx0 = pack2(-pos[3 * i0 + 0], -pos[3 * i0 + 0]);
    const u64 ny0 = pack2(-pos[3 * i0 + 1], -pos[3 * i0 + 1]);
    const u64 nz0 = pack2(-pos[3 * i0 + 2], -pos[3 * i0 + 2]);
    const u64 nx1 = pack2(-pos[3 * i1 + 0], -pos[3 * i1 + 0]);
    const u64 ny1 = pack2(-pos[3 * i1 + 1], -pos[3 * i1 + 1]);
    const u64 nz1 = pack2(-pos[3 * i1 + 2], -pos[3 * i1 + 2]);
    const u64 eps22 = pack2(EPS2, EPS2);

    u64 ax0 = 0ull, ay0 = 0ull, az0 = 0ull;
    u64 ax1 = 0ull, ay1 = 0ull, az1 = 0ull;

#pragma unroll 4
    for (int t = 0; t < JP; ++t) {
        const u64 px = sx[t];              // LDS.64 broadcast feeds 4 pairs
        const u64 py = sy[t];
        const u64 pz = sz[t];
        const u64 pm = sm[t];

        // chain 0
        u64 dx0 = f2add(px, nx0);
        u64 dy0 = f2add(py, ny0);
        u64 dz0 = f2add(pz, nz0);
        // chain 1 (independent)
        u64 dx1 = f2add(px, nx1);
        u64 dy1 = f2add(py, ny1);
        u64 dz1 = f2add(pz, nz1);

        u64 r20 = f2fma(dx0, dx0, f2fma(dy0, dy0, f2fma(dz0, dz0, eps22)));
        u64 r21 = f2fma(dx1, dx1, f2fma(dy1, dy1, f2fma(dz1, dz1, eps22)));

        float a, b;
        unpack2(r20, a, b);
        u64 inv0 = pack2(rsq_mufu(a), rsq_mufu(b));
        unpack2(r21, a, b);
        u64 inv1 = pack2(rsq_mufu(a), rsq_mufu(b));

        u64 s0 = f2mul(pm, f2mul(f2mul(inv0, inv0), inv0));
        u64 s1 = f2mul(pm, f2mul(f2mul(inv1, inv1), inv1));

        ax0 = f2fma(s0, dx0, ax0);
        ay0 = f2fma(s0, dy0, ay0);
        az0 = f2fma(s0, dz0, az0);
        ax1 = f2fma(s1, dx1, ax1);
        ay1 = f2fma(s1, dy1, ay1);
        az1 = f2fma(s1, dz1, az1);
    }

    float l, h;
    unpack2(ax0, l, h); atomicAdd(&out[3 * i0 + 0], l + h);
    unpack2(ay0, l, h); atomicAdd(&out[3 * i0 + 1], l + h);
    unpack2(az0, l, h); atomicAdd(&out[3 * i0 + 2], l + h);
    unpack2(ax1, l, h); atomicAdd(&out[3 * i1 + 0], l + h);
    unpack2(ay1, l, h); atomicAdd(&out[3 * i1 + 1], l + h);
    unpack2(az1, l, h); atomicAdd(&out[3 * i1 + 2], l + h);
}

extern "C" void kernel_launch(void* const* d_in, const int* in_sizes, int n_in,
                              void* d_out, int out_size) {
    const float* pos  = (const float*)d_in[0];   // [N,3] float32
    const float* mass = (const float*)d_in[1];   // [N]   float32
    float* out = (float*)d_out;                  // [N,3] float32

    const int n = in_sizes[0] / 3;               // 8192

    zero_out_kernel<<<(out_size + 255) / 256, 256>>>(out, out_size);

    dim3 grid(n / (BLOCK * IPT), n / JCHUNK);    // 16 x 64 = 1024 CTAs
    nbody_forces_kernel<<<grid, BLOCK>>>(pos, mass, out);
}